// round 4
// baseline (speedup 1.0000x reference)
#include <cuda_runtime.h>
#include <cstdint>
#include <cstddef>

#define BB 128
#define LL 1024
#define TT 64
#define DD 256

// Scratch: emissions [B, L, T] fp32 (33.5 MB). Static __device__ array (no allocs).
__device__ float g_emis[BB * LL * TT];

// ---------------- f32x2 packed-math helpers (sm_103a) ----------------
__device__ __forceinline__ unsigned long long fma2(unsigned long long a, unsigned long long b, unsigned long long c) {
    unsigned long long d;
    asm("fma.rn.f32x2 %0, %1, %2, %3;" : "=l"(d) : "l"(a), "l"(b), "l"(c));
    return d;
}
__device__ __forceinline__ unsigned long long add2(unsigned long long a, unsigned long long b) {
    unsigned long long d;
    asm("add.rn.f32x2 %0, %1, %2;" : "=l"(d) : "l"(a), "l"(b));
    return d;
}
__device__ __forceinline__ unsigned long long pack2(float lo, float hi) {
    unsigned long long d;
    asm("mov.b64 %0, {%1, %2};" : "=l"(d) : "f"(lo), "f"(hi));
    return d;
}
__device__ __forceinline__ float2 unpack2(unsigned long long v) {
    float lo, hi;
    asm("mov.b64 {%0, %1}, %2;" : "=f"(lo), "=f"(hi) : "l"(v));
    return make_float2(lo, hi);
}

// ---------------- Kernel A: emissions = embed[x] @ W + b ----------------
// Grid: 1024 CTAs x 256 threads. Each CTA: 128 tokens x 64 labels, K=256.
// SMEM: full W [256][64] (64KB) + embed tile [128][68-padded] per 64-wide K chunk.
// Thread tile: 4 tokens x 8 labels, accumulated as 16 f32x2 pairs.

#define ESTRIDE 68
#define SMEM_A_BYTES ((16384 + 128 * ESTRIDE) * 4 + 128 * 4)

__global__ void __launch_bounds__(256, 2)
emis_kernel(const int* __restrict__ x, const float* __restrict__ embed,
            const float* __restrict__ W, const float* __restrict__ bias,
            float* __restrict__ out_scalar) {
    extern __shared__ float sm[];
    float* w_sh = sm;                       // [256][64]
    float* e_sh = sm + 16384;               // [128][ESTRIDE]
    int* xs = (int*)(e_sh + 128 * ESTRIDE); // [128]

    int tid = threadIdx.x;
    if (blockIdx.x == 0 && tid == 0) *out_scalar = 0.0f;  // kernel B accumulates into this

    int tok_base = blockIdx.x * 128;

    // Load all of W (coalesced float4)
    {
        const float4* src = (const float4*)W;
        float4* dst = (float4*)w_sh;
        #pragma unroll
        for (int i = 0; i < 16; i++) dst[tid + 256 * i] = src[tid + 256 * i];
    }
    if (tid < 128) xs[tid] = x[tok_base + tid];
    __syncthreads();

    const int lg = tid & 7;    // label group: labels lg*8 .. lg*8+7
    const int tg = tid >> 3;   // token group: tokens tg*4 .. tg*4+3
    const int warp = tid >> 5, lane = tid & 31;

    unsigned long long acc[4][4];
    #pragma unroll
    for (int t = 0; t < 4; t++)
        #pragma unroll
        for (int q = 0; q < 4; q++) acc[t][q] = 0ull;

    for (int c = 0; c < 4; c++) {
        const int c0 = c * 64;
        // Gather embed tile: per warp-iter, 2 tokens x 64 floats (fully coalesced float4)
        #pragma unroll
        for (int pr = warp; pr < 64; pr += 8) {
            int tl = pr * 2 + (lane >> 4);
            int d4 = lane & 15;
            float4 v = *(const float4*)(embed + (size_t)xs[tl] * DD + c0 + d4 * 4);
            *(float4*)&e_sh[tl * ESTRIDE + d4 * 4] = v;
        }
        __syncthreads();

        #pragma unroll 8
        for (int d = 0; d < 64; d++) {
            const ulonglong2* wrow = (const ulonglong2*)&w_sh[(c0 + d) * 64 + (lg << 3)];
            ulonglong2 w01 = wrow[0];  // labels (0,1),(2,3)
            ulonglong2 w23 = wrow[1];  // labels (4,5),(6,7)
            #pragma unroll
            for (int t = 0; t < 4; t++) {
                float e = e_sh[(tg * 4 + t) * ESTRIDE + d];
                unsigned long long e2 = pack2(e, e);
                acc[t][0] = fma2(e2, w01.x, acc[t][0]);
                acc[t][1] = fma2(e2, w01.y, acc[t][1]);
                acc[t][2] = fma2(e2, w23.x, acc[t][2]);
                acc[t][3] = fma2(e2, w23.y, acc[t][3]);
            }
        }
        __syncthreads();
    }

    float bb[8];
    #pragma unroll
    for (int k = 0; k < 8; k++) bb[k] = bias[(lg << 3) + k];

    #pragma unroll
    for (int t = 0; t < 4; t++) {
        int tokg = tok_base + tg * 4 + t;
        float2 p0 = unpack2(acc[t][0]);
        float2 p1 = unpack2(acc[t][1]);
        float2 p2 = unpack2(acc[t][2]);
        float2 p3 = unpack2(acc[t][3]);
        float4* o = (float4*)(g_emis + (size_t)tokg * TT + (lg << 3));
        o[0] = make_float4(p0.x + bb[0], p0.y + bb[1], p1.x + bb[2], p1.y + bb[3]);
        o[1] = make_float4(p2.x + bb[4], p2.y + bb[5], p3.x + bb[6], p3.y + bb[7]);
    }
}

// ---------------- Kernel B: CRF NLL ----------------
// Grid: 128 CTAs (one per sequence) x 64 threads (one per label).
// Recursion kept centered: a_j = alpha_j - C; per step:
//   p_j = exp(a_j); s_j = sum_i p_i * E[i][j]  (E = exp(trans), in registers)
//   m = log(sum of p over labels 16..47)  (cheap uniform normalizer, bounded)
//   a_j = log(s_j) + emit_j - m;  C += m
// Gold path score + final logsumexp fused; per-CTA atomicAdd(log_z - score).

__global__ void __launch_bounds__(64)
crf_kernel(const int* __restrict__ tags, const float* __restrict__ trans,
           float* __restrict__ out) {
    __shared__ float trans_sh[64 * 64];
    __shared__ __align__(16) float shp[2][64];
    __shared__ float red[64];

    const int j = threadIdx.x;
    const int b = blockIdx.x;

    #pragma unroll
    for (int idx = j; idx < 4096; idx += 64) trans_sh[idx] = trans[idx];
    __syncthreads();

    // E column j in registers as 32 f32x2 pairs: E2[i2] = (exp(trans[2i2][j]), exp(trans[2i2+1][j]))
    unsigned long long E2[32];
    #pragma unroll
    for (int i2 = 0; i2 < 32; i2++) {
        float e0 = __expf(trans_sh[(2 * i2) * 64 + j]);
        float e1 = __expf(trans_sh[(2 * i2 + 1) * 64 + j]);
        E2[i2] = pack2(e0, e1);
    }

    const float* em = g_emis + (size_t)b * LL * TT;
    const int* tgp = tags + b * LL;

    float em0 = em[j];
    int tag0 = tgp[0];
    float a = trans_sh[j] + em0;              // trans[START=0][j] + emissions[0][j]
    float eacc = (j == tag0) ? em0 : 0.0f;    // gold emission partial
    float tacc = 0.0f;                        // gold transition sum (identical on all threads)
    int ptag = tag0;
    float C = 0.0f;

    // 4-deep prefetch of emissions row + tag
    float embuf[4];
    int tagbuf[4];
    #pragma unroll
    for (int k = 1; k <= 4; k++) { embuf[k & 3] = em[k * 64 + j]; tagbuf[k & 3] = tgp[k]; }

    #pragma unroll 4
    for (int t = 1; t < LL; t++) {
        float emt = embuf[t & 3];
        int tt = tagbuf[t & 3];
        if (t + 4 < LL) { embuf[t & 3] = em[(t + 4) * 64 + j]; tagbuf[t & 3] = tgp[t + 4]; }

        float p = __expf(a);
        shp[t & 1][j] = p;
        __syncthreads();

        const ulonglong2* sp = (const ulonglong2*)shp[t & 1];
        unsigned long long aA = 0, aB = 0, aC = 0, aD = 0, s0 = 0, s1 = 0;
        #pragma unroll
        for (int q = 0; q < 16; q++) {
            ulonglong2 u = sp[q];  // p pairs (4q,4q+1) and (4q+2,4q+3)
            if (q & 1) { aB = fma2(u.x, E2[2 * q], aB); aD = fma2(u.y, E2[2 * q + 1], aD); }
            else       { aA = fma2(u.x, E2[2 * q], aA); aC = fma2(u.y, E2[2 * q + 1], aC); }
            if (q >= 4 && q < 12) { s0 = add2(s0, u.x); s1 = add2(s1, u.y); }  // labels 16..47
        }
        float2 sf = unpack2(add2(add2(aA, aB), add2(aC, aD)));
        float s = sf.x + sf.y;
        float2 Sf = unpack2(add2(s0, s1));
        float S = Sf.x + Sf.y;   // > 0 always (healthy labels in subset)

        float m = __logf(S);
        a = __logf(s) + emt - m;  // s == 0 -> -inf -> exp -> 0 (matches fp32 reference underflow)
        C += m;

        eacc += (j == tt) ? emt : 0.0f;
        tacc += trans_sh[ptag * 64 + tt];
        ptag = tt;
    }

    // log_z = C + log( sum_j exp(a_j + trans[j][END=1]) )
    float vend = __expf(a + trans_sh[j * 64 + 1]);
    shp[0][j] = vend;
    red[j] = eacc;
    __syncthreads();

    if (j == 0) {
        float Z = 0.0f, eg = 0.0f;
        #pragma unroll
        for (int k = 0; k < 64; k++) { Z += shp[0][k]; eg += red[k]; }
        float logz = C + __logf(Z);
        float score = eg + tacc + trans_sh[tag0] + trans_sh[ptag * 64 + 1];
        atomicAdd(out, logz - score);  // out = -sum(scores - log_z)
    }
}

// ---------------- launch ----------------
extern "C" void kernel_launch(void* const* d_in, const int* in_sizes, int n_in,
                              void* d_out, int out_size) {
    const int*   x     = (const int*)d_in[0];
    const int*   tags  = (const int*)d_in[1];
    // d_in[2] = mask (ignored by reference CRF)
    const float* embed = (const float*)d_in[3];
    const float* W     = (const float*)d_in[4];
    const float* bias  = (const float*)d_in[5];
    const float* trans = (const float*)d_in[6];
    float* out = (float*)d_out;

    cudaFuncSetAttribute(emis_kernel, cudaFuncAttributeMaxDynamicSharedMemorySize, SMEM_A_BYTES);

    emis_kernel<<<(BB * LL) / 128, 256, SMEM_A_BYTES>>>(x, embed, W, bias, out);
    crf_kernel<<<BB, 64>>>(tags, trans, out);
}